// round 11
// baseline (speedup 1.0000x reference)
#include <cuda_runtime.h>
#include <cuda_bf16.h>

// SpatialMaxpool2d: x (32, 69, 128, 128) fp32, k=2, stride=2.
// Out (32, 69, 64, 64):
//   ch 0..63  : 2x2 maxpool of x[:, 0:64]
//   ch 64..65 : weighted window mean of x[:, 64:66]
//   ch 66..67 : weighted var  (x[:,66:68]·q + sum q*(u-mean)^2)
//   ch 68     : weighted cov  (x[:,68]·q + sum q^2*(u0-m0)*(u1-m1))
// Window weight q_p = A_p / sum_p A_p, A_p = sum_c |x[b,c,p]| over ALL 69 channels.
//
// R11: undiluted phase separation. 32-channel chunks; loads are consumed
// immediately into abs-accumulators + a 1-reg max per channel (short live
// ranges -> ptxas hoists loads, deep MLP), then a burst of 32 stores.
// R8 (chunk 16, full staging) was collapsed by ptxas to regs=40; this form
// stages only the 32 store VALUES (cheap) so the store burst survives.
// R2 lesson: no cache hints. R4 lesson: float2/256thr geometry is best.

#define C_TOTAL 69
#define CS      64
#define H_IN    128
#define W_IN    128
#define H_OUT   64
#define W_OUT   64
#define HW_IN   (H_IN * W_IN)      // 16384
#define HW_OUT  (H_OUT * W_OUT)    // 4096
#define CHUNK   32

__global__ void __launch_bounds__(256)
spatial_maxpool_kernel(const float* __restrict__ x, float* __restrict__ out, int total)
{
    int idx = blockIdx.x * blockDim.x + threadIdx.x;
    if (idx >= total) return;

    int j = idx & (W_OUT - 1);
    int i = (idx >> 6) & (H_OUT - 1);
    int b = idx >> 12;

    const float* xb   = x + (size_t)b * C_TOTAL * HW_IN;
    const float* row0 = xb + (2 * i) * W_IN + 2 * j;       // top row of 2x2 window
    const float* row1 = row0 + W_IN;                        // bottom row
    float* ob = out + (size_t)b * C_TOTAL * HW_OUT + i * W_OUT + j;

    // |.| accumulators for the 4 window pixels: (0,0) (0,1) (1,0) (1,1)
    float a0 = 0.f, a1 = 0.f, a2 = 0.f, a3 = 0.f;

    // ---- pooled channels 0..63: 32-channel read/compute phase, then 32-store burst ----
    #pragma unroll
    for (int cb = 0; cb < CS; cb += CHUNK) {
        float mx[CHUNK];
        #pragma unroll
        for (int t = 0; t < CHUNK; ++t) {
            float2 r0 = __ldg((const float2*)(row0 + (cb + t) * HW_IN));
            float2 r1 = __ldg((const float2*)(row1 + (cb + t) * HW_IN));
            a0 += fabsf(r0.x); a1 += fabsf(r0.y);
            a2 += fabsf(r1.x); a3 += fabsf(r1.y);
            mx[t] = fmaxf(fmaxf(r0.x, r0.y), fmaxf(r1.x, r1.y));
        }
        #pragma unroll
        for (int t = 0; t < CHUNK; ++t)
            ob[(cb + t) * HW_OUT] = mx[t];
    }

    // ---- stat channels 64..68: keep window values in registers ----
    float v[5][4];
    #pragma unroll
    for (int t = 0; t < 5; ++t) {
        int c = CS + t;
        float2 r0 = __ldg((const float2*)(row0 + c * HW_IN));
        float2 r1 = __ldg((const float2*)(row1 + c * HW_IN));
        v[t][0] = r0.x; v[t][1] = r0.y; v[t][2] = r1.x; v[t][3] = r1.y;
        a0 += fabsf(r0.x); a1 += fabsf(r0.y);
        a2 += fabsf(r1.x); a3 += fabsf(r1.y);
    }

    // normalized window weights (scale by 1/sqrt(cs) cancels)
    float s = a0 + a1 + a2 + a3;
    float inv = 1.0f / s;
    float q0 = a0 * inv, q1 = a1 * inv, q2 = a2 * inv, q3 = a3 * inv;

    // means of u-channels (64, 65)
    float m0 = v[0][0] * q0 + v[0][1] * q1 + v[0][2] * q2 + v[0][3] * q3;
    float m1 = v[1][0] * q0 + v[1][1] * q1 + v[1][2] * q2 + v[1][3] * q3;

    // var = x[66+c]·q + sum q*(u - m)^2
    float d00 = v[0][0] - m0, d01 = v[0][1] - m0, d02 = v[0][2] - m0, d03 = v[0][3] - m0;
    float d10 = v[1][0] - m1, d11 = v[1][1] - m1, d12 = v[1][2] - m1, d13 = v[1][3] - m1;

    float var0 = v[2][0] * q0 + v[2][1] * q1 + v[2][2] * q2 + v[2][3] * q3
               + d00 * d00 * q0 + d01 * d01 * q1 + d02 * d02 * q2 + d03 * d03 * q3;
    float var1 = v[3][0] * q0 + v[3][1] * q1 + v[3][2] * q2 + v[3][3] * q3
               + d10 * d10 * q0 + d11 * d11 * q1 + d12 * d12 * q2 + d13 * d13 * q3;

    // cov = x[68]·q + sum q^2*(u0-m0)*(u1-m1)
    float cov = v[4][0] * q0 + v[4][1] * q1 + v[4][2] * q2 + v[4][3] * q3
              + d00 * d10 * q0 * q0 + d01 * d11 * q1 * q1
              + d02 * d12 * q2 * q2 + d03 * d13 * q3 * q3;

    ob[(CS + 0) * HW_OUT] = m0;
    ob[(CS + 1) * HW_OUT] = m1;
    ob[(CS + 2) * HW_OUT] = var0;
    ob[(CS + 3) * HW_OUT] = var1;
    ob[(CS + 4) * HW_OUT] = cov;
}

extern "C" void kernel_launch(void* const* d_in, const int* in_sizes, int n_in,
                              void* d_out, int out_size)
{
    const float* x = (const float*)d_in[0];
    float* out = (float*)d_out;
    int total = 32 * H_OUT * W_OUT;  // 131072 output pixels
    int threads = 256;
    int blocks = (total + threads - 1) / threads;  // 512 blocks
    spatial_maxpool_kernel<<<blocks, threads>>>(x, out, total);
}